// round 13
// baseline (speedup 1.0000x reference)
#include <cuda_runtime.h>
#include <cuda_fp16.h>
#include <cstdint>

// ---------------------------------------------------------------------------
// B=32, N=1024 -> T=32768 tokens, d=256, C=1024
// o_cls (T x C) = l2norm(x) @ l2norm(e,0)
// o_seq (T x C) = l2norm(x) @ l2norm(w,0)
// new_db (d x C) = EMA codebook update
// GEMM: fp16 mma.sync, tile 128x128, 4 warps (warp tile 64x64), 128 thr/CTA,
// 2 CTAs/SM at <=256 regs. 3-stage cp.async pipeline + register
// double-buffered ldmatrix fragments (fits: 128 acc + 64 frag + addr < 256).
// ---------------------------------------------------------------------------

#define T_TOKENS 32768
#define DIM      256
#define NCLS     1024
#define ALPHA_F  0.9f
#define EPS_F    1.19e-07f

// GEMM tiling
#define BM 128
#define BN 128
#define BK 64                       // 64 fp16 = 128 bytes/row (SW128 atom)
#define STAGE  32768                // A 16KB + B 16KB
#define GEMM_SMEM (1024 + 3 * STAGE)   // ~97KB per CTA; x2 CTAs = 194KB/SM

// ---------------- device scratch (allocation-free) -------------------------
__device__ __align__(16) __half g_x16 [(size_t)T_TOKENS * DIM];   // normalized x, fp16
__device__ __align__(16) __half g_bt16[(size_t)2 * NCLS * DIM];   // [class][k]: rows 0..1023 = en, 1024..2047 = wn
__device__ float g_num[DIM * NCLS];
__device__ float g_cnt[NCLS];
__device__ float g_sumA[NCLS];
__device__ float g_sumNA[NCLS];
__device__ float g_colsum[2 * NCLS];   // [0..1023]=e column sq-sums, [1024..2047]=w

// ---------------- PTX helpers (portable, sm_80+) ---------------------------
__device__ __forceinline__ uint32_t smem_u32(const void* p) {
    uint32_t a;
    asm("{ .reg .u64 t; cvta.to.shared.u64 t, %1; cvt.u32.u64 %0, t; }" : "=r"(a) : "l"(p));
    return a;
}
__device__ __forceinline__ void cpa16(uint32_t s, const void* g) {
    asm volatile("cp.async.cg.shared.global [%0], [%1], 16;" :: "r"(s), "l"(g));
}
#define CP_COMMIT() asm volatile("cp.async.commit_group;" ::: "memory")
#define CP_WAIT(n)  asm volatile("cp.async.wait_group %0;" :: "n"(n) : "memory")

#define LDSM_X4(r0, r1, r2, r3, addr) \
    asm volatile("ldmatrix.sync.aligned.m8n8.x4.shared.b16 {%0,%1,%2,%3}, [%4];" \
        : "=r"(r0), "=r"(r1), "=r"(r2), "=r"(r3) : "r"(addr))

#define MMA16816(d, a, b) \
    asm volatile("mma.sync.aligned.m16n8k16.row.col.f32.f16.f16.f32 " \
        "{%0,%1,%2,%3},{%4,%5,%6,%7},{%8,%9},{%0,%1,%2,%3};" \
        : "+f"((d)[0]), "+f"((d)[1]), "+f"((d)[2]), "+f"((d)[3]) \
        : "r"((a)[0]), "r"((a)[1]), "r"((a)[2]), "r"((a)[3]), \
          "r"((b)[0]), "r"((b)[1]))

__device__ __forceinline__ uint32_t sw128(uint32_t bo) {
    return bo ^ ((bo >> 3) & 0x70);
}

// ---------------------------------------------------------------------------
// 0) zero accumulators
// ---------------------------------------------------------------------------
__global__ void zero_kernel() {
    int i = blockIdx.x * blockDim.x + threadIdx.x;
    int stride = gridDim.x * blockDim.x;
    for (int j = i; j < DIM * NCLS; j += stride) g_num[j] = 0.0f;
    if (i < 2 * NCLS) g_colsum[i] = 0.0f;
    if (i < NCLS) { g_cnt[i] = 0.0f; g_sumA[i] = 0.0f; g_sumNA[i] = 0.0f; }
}

// ---------------------------------------------------------------------------
// 1) per-token l2 normalize -> fp16 + class-conditioned scatter (fused)
// ---------------------------------------------------------------------------
__global__ void norm_x_kernel(const float* __restrict__ emb,
                              const int*   __restrict__ labels,
                              const float* __restrict__ anc)
{
    int gwarp = (blockIdx.x * blockDim.x + threadIdx.x) >> 5;
    int lane  = threadIdx.x & 31;
    if (gwarp >= T_TOKENS) return;

    const float* src = emb + (size_t)gwarp * DIM + lane * 8;
    float v[8];
    float4 v0 = *(const float4*)(src);
    float4 v1 = *(const float4*)(src + 4);
    v[0]=v0.x; v[1]=v0.y; v[2]=v0.z; v[3]=v0.w;
    v[4]=v1.x; v[5]=v1.y; v[6]=v1.z; v[7]=v1.w;

    float s = 0.f;
    #pragma unroll
    for (int j = 0; j < 8; j++) s += v[j] * v[j];
    #pragma unroll
    for (int o = 16; o > 0; o >>= 1) s += __shfl_xor_sync(0xFFFFFFFFu, s, o);
    float r = rsqrtf(fmaxf(s, 1e-12f));

    union { __half h[8]; float4 f; } H;
    #pragma unroll
    for (int j = 0; j < 8; j++) {
        v[j] *= r;
        H.h[j] = __float2half_rn(v[j]);
    }
    *(float4*)(g_x16 + (size_t)gwarp * DIM + lane * 8) = H.f;

    float a = anc[gwarp];
    int   c = labels[gwarp];
    if (a > 0.5f) {
        int d0 = lane * 8;
        #pragma unroll
        for (int j = 0; j < 8; j++)
            atomicAdd(&g_num[(d0 + j) * NCLS + c], v[j]);
    }
    if (lane == 0) {
        atomicAdd(&g_cnt[c],   1.0f);
        atomicAdd(&g_sumA[c],  a);
        atomicAdd(&g_sumNA[c], 1.0f - a);
    }
}

// ---------------------------------------------------------------------------
// 2a) column squared-sums of e/w (parallel, coalesced)
// ---------------------------------------------------------------------------
__global__ void colsum_kernel(const float* __restrict__ w,
                              const float* __restrict__ e)
{
    const float* src = (blockIdx.z == 0) ? e : w;
    int col = blockIdx.x * 256 + threadIdx.x;
    int d0  = blockIdx.y * 8;
    float s = 0.0f;
    #pragma unroll
    for (int j = 0; j < 8; j++) {
        float v = src[(size_t)(d0 + j) * NCLS + col];
        s += v * v;
    }
    atomicAdd(&g_colsum[blockIdx.z * NCLS + col], s);
}

// ---------------------------------------------------------------------------
// 2b) scale + transpose + fp16 convert: src [d][c] -> g_bt16 [c][d]
// ---------------------------------------------------------------------------
__global__ void build_bt_kernel(const float* __restrict__ w,
                                const float* __restrict__ e)
{
    __shared__ float tile[32][33];
    __shared__ float rs[32];

    const float* src = (blockIdx.z == 0) ? e : w;
    const int c0 = blockIdx.x * 32;
    const int d0 = blockIdx.y * 32;
    const int tx = threadIdx.x & 31;
    const int ty = threadIdx.x >> 5;

    if (threadIdx.x < 32)
        rs[threadIdx.x] = rsqrtf(fmaxf(g_colsum[blockIdx.z * NCLS + c0 + threadIdx.x], 1e-12f));

    #pragma unroll
    for (int i = 0; i < 4; i++) {
        int dl = ty + i * 8;
        tile[dl][tx] = src[(size_t)(d0 + dl) * NCLS + c0 + tx];
    }
    __syncthreads();

    #pragma unroll
    for (int i = 0; i < 4; i++) {
        int cl = ty + i * 8;
        float v = tile[tx][cl] * rs[cl];
        g_bt16[(size_t)(blockIdx.z * NCLS + c0 + cl) * DIM + d0 + tx] = __float2half_rn(v);
    }
}

// ---------------------------------------------------------------------------
// 3) fp16 HMMA GEMM: tile 128x128, 4 warps (warp tile 64x64), 128 thr/CTA,
//    2 CTAs/SM, 3-stage cp.async pipeline, reg double-buffered fragments.
//    grid = (256, 16): blockIdx.y < 8 -> o_cls, else o_seq.
// ---------------------------------------------------------------------------
__global__ __launch_bounds__(128, 2)
void gemm_hmma_kernel(float* __restrict__ o_cls, float* __restrict__ o_seq)
{
    extern __shared__ char dsm[];
    const int tid    = threadIdx.x;
    const int lane   = tid & 31;
    const int wid    = tid >> 5;    // 0..3
    const int warp_m = wid & 1;     // rows wm*64
    const int warp_n = wid >> 1;    // cols wn*64

    const int m0 = blockIdx.x * BM;
    const int n0 = blockIdx.y * BN;              // fused column space [0,2048)
    float* O = (n0 < NCLS) ? o_cls : o_seq;
    const int ncol0 = n0 & (NCLS - 1);

    uint32_t raw  = smem_u32(dsm);
    uint32_t dynu = (raw + 1023u) & ~1023u;

    // ---- per-thread ldmatrix base addresses (kk = 0), swizzled -------------
    // kk offset (kk*32, bits 5-6) applied by XOR: commutes with SW128 xor
    // because seg*16 (bit 4) and kk*32 (bits 5-6) are bit-disjoint.
    uint32_t a_base[4], b_base[4];
    {
        #pragma unroll
        for (int mf = 0; mf < 4; mf++) {
            int row = warp_m * 64 + mf * 16 + (lane & 15);
            a_base[mf] = sw128((uint32_t)(row * 128 + ((lane >> 4) * 16)));
        }
        int g = lane >> 3;
        #pragma unroll
        for (int bf = 0; bf < 4; bf++) {
            int row = warp_n * 64 + bf * 16 + (g >> 1) * 8 + (lane & 7);
            b_base[bf] = 16384u + sw128((uint32_t)(row * 128 + ((g & 1) * 16)));
        }
    }

    // ---- stage loader: chunk k0=c*64 -> stage (A @0, B @16384) -------------
    const int lr  = tid >> 3;       // 0..15
    const int lsg = tid & 7;        // 16B segment in row
    auto load_stage = [&](int chunk, int stage) {
        uint32_t sb = dynu + stage * STAGE;
        const int k0 = chunk * BK;
        #pragma unroll
        for (int i = 0; i < 8; i++) {
            int r = lr + i * 16;                 // 0..127
            uint32_t sw = sw128((uint32_t)(r * 128 + lsg * 16));
            cpa16(sb + sw,          g_x16  + (size_t)(m0 + r) * DIM + k0 + lsg * 8);
            cpa16(sb + 16384 + sw,  g_bt16 + (size_t)(n0 + r) * DIM + k0 + lsg * 8);
        }
        CP_COMMIT();
    };

    float acc[4][8][4] = {};   // [mfrag][nfrag][4] = 128 regs

    uint32_t afrag[2][4][4];   // [buf][mf][4]  = 32 regs
    uint32_t bfrag[2][8][2];   // [buf][nf][2]  = 32 regs

    auto ldfrags = [&](uint32_t sb, int kk, int buf) {
        uint32_t koff = (uint32_t)(kk * 32);
        #pragma unroll
        for (int mf = 0; mf < 4; mf++)
            LDSM_X4(afrag[buf][mf][0], afrag[buf][mf][1],
                    afrag[buf][mf][2], afrag[buf][mf][3],
                    (sb + a_base[mf]) ^ koff);
        #pragma unroll
        for (int bf = 0; bf < 4; bf++) {
            uint32_t r0, r1, r2, r3;
            LDSM_X4(r0, r1, r2, r3, (sb + b_base[bf]) ^ koff);
            bfrag[buf][bf*2][0]   = r0; bfrag[buf][bf*2][1]   = r1;
            bfrag[buf][bf*2+1][0] = r2; bfrag[buf][bf*2+1][1] = r3;
        }
    };

    // ---- compute one 64-K chunk with reg double buffering -------------------
    auto compute = [&](uint32_t sb) {
        ldfrags(sb, 0, 0);
        #pragma unroll
        for (int kk = 0; kk < 4; kk++) {
            int cur = kk & 1;
            if (kk < 3) ldfrags(sb, kk + 1, cur ^ 1);
            #pragma unroll
            for (int mf = 0; mf < 4; mf++)
                #pragma unroll
                for (int nf = 0; nf < 8; nf++)
                    MMA16816(acc[mf][nf], afrag[cur][mf], bfrag[cur][nf]);
        }
    };

    // ---- pipeline: 3 stages, 4 chunks ---------------------------------------
    load_stage(0, 0);        // g0
    load_stage(1, 1);        // g1
    load_stage(2, 2);        // g2

    CP_WAIT(2); __syncthreads();       // g0 done
    compute(dynu);
    __syncthreads();                   // all warps done reading stage 0
    load_stage(3, 0);                  // g3

    CP_WAIT(2); __syncthreads();       // g1 done
    compute(dynu + STAGE);

    CP_WAIT(1); __syncthreads();       // g2 done
    compute(dynu + 2 * STAGE);

    CP_WAIT(0); __syncthreads();       // g3 done
    compute(dynu);

    // ---- epilogue: vectorized fp32 stores -----------------------------------
    #pragma unroll
    for (int mf = 0; mf < 4; mf++) {
        int row = m0 + warp_m * 64 + mf * 16 + (lane >> 2);
        #pragma unroll
        for (int nf = 0; nf < 8; nf++) {
            int col = ncol0 + warp_n * 64 + nf * 8 + 2 * (lane & 3);
            *(float2*)(O + (size_t)row * NCLS + col) =
                make_float2(acc[mf][nf][0], acc[mf][nf][1]);
            *(float2*)(O + (size_t)(row + 8) * NCLS + col) =
                make_float2(acc[mf][nf][2], acc[mf][nf][3]);
        }
    }
}

// ---------------------------------------------------------------------------
// 4) finalize new_db
// ---------------------------------------------------------------------------
__global__ void finalize_kernel(const float* __restrict__ w,
                                const float* __restrict__ e,
                                float* __restrict__ db)
{
    int idx = blockIdx.x * blockDim.x + threadIdx.x;
    if (idx >= DIM * NCLS) return;
    int c = idx & (NCLS - 1);

    float cnt    = g_cnt[c];
    float negAnc = (g_sumA[c]  > 0.5f) ? 1.0f : 0.0f;
    float posAnc = (g_sumNA[c] > 0.5f) ? 1.0f : 0.0f;
    float negCls = (cnt > 0.5f) ? 0.0f : 1.0f;

    float wv = w[idx];
    float ev = e[idx];
    float ema = 0.1f * (g_num[idx] / (cnt + EPS_F));
    db[idx] = ALPHA_F * wv * negAnc + ema + wv * negCls + ev * posAnc;
}

// ---------------------------------------------------------------------------
// launch
// ---------------------------------------------------------------------------
extern "C" void kernel_launch(void* const* d_in, const int* in_sizes, int n_in,
                              void* d_out, int out_size)
{
    const float* emb = (const float*)d_in[0];
    const int*   obj = (const int*)  d_in[2];
    const float* anc = (const float*)d_in[3];
    const float* w   = (const float*)d_in[5];
    const float* e   = (const float*)d_in[6];

    float* out   = (float*)d_out;
    float* o_cls = out;
    float* o_seq = out + (size_t)T_TOKENS * NCLS;
    float* db    = out + (size_t)2 * T_TOKENS * NCLS;

    cudaFuncSetAttribute(gemm_hmma_kernel,
                         cudaFuncAttributeMaxDynamicSharedMemorySize, GEMM_SMEM);

    zero_kernel<<<512, 256>>>();
    norm_x_kernel<<<(T_TOKENS * 32) / 256, 256>>>(emb, obj, anc);
    colsum_kernel<<<dim3(4, 32, 2), 256>>>(w, e);
    build_bt_kernel<<<dim3(32, 8, 2), 256>>>(w, e);

    dim3 grid(T_TOKENS / BM, 2 * NCLS / BN);     // (256, 16)
    gemm_hmma_kernel<<<grid, 128, GEMM_SMEM>>>(o_cls, o_seq);

    finalize_kernel<<<(DIM * NCLS) / 256, 256>>>(w, e, db);
}

// round 14
// speedup vs baseline: 1.0591x; 1.0591x over previous
#include <cuda_runtime.h>
#include <cuda_fp16.h>
#include <cstdint>

// ---------------------------------------------------------------------------
// B=32, N=1024 -> T=32768 tokens, d=256, C=1024
// o_cls (T x C) = l2norm(x) @ l2norm(e,0)
// o_seq (T x C) = l2norm(x) @ l2norm(w,0)
// new_db (d x C) = EMA codebook update
// GEMM: fp16 mma.sync, tile 128x128, 4 warps (warp tile 64x64), 128 thr/CTA,
// 2 CTAs/SM (R12 config — best measured). Launch graph compacted to 4:
//   prep (zero + colsum partials) -> norm_x -> build_bt -> gemm(+finalize)
// finalize runs inside gemm CTAs, hidden under the cp.async prologue.
// ---------------------------------------------------------------------------

#define T_TOKENS 32768
#define DIM      256
#define NCLS     1024
#define ALPHA_F  0.9f
#define EPS_F    1.19e-07f

// GEMM tiling
#define BM 128
#define BN 128
#define BK 64                       // 64 fp16 = 128 bytes/row (SW128 atom)
#define STAGE  32768                // A 16KB + B 16KB
#define GEMM_SMEM (1024 + 3 * STAGE)   // ~97KB per CTA; x2 CTAs = 194KB/SM

// ---------------- device scratch (allocation-free) -------------------------
__device__ __align__(16) __half g_x16 [(size_t)T_TOKENS * DIM];   // normalized x, fp16
__device__ __align__(16) __half g_bt16[(size_t)2 * NCLS * DIM];   // [class][k]: rows 0..1023 = en, 1024..2047 = wn
__device__ float g_num[DIM * NCLS];
__device__ float g_cnt[NCLS];
__device__ float g_sumA[NCLS];
__device__ float g_sumNA[NCLS];
__device__ float g_cs_part[2 * 32 * NCLS];   // colsum partials [z][dblk][col]

// ---------------- PTX helpers (portable, sm_80+) ---------------------------
__device__ __forceinline__ uint32_t smem_u32(const void* p) {
    uint32_t a;
    asm("{ .reg .u64 t; cvta.to.shared.u64 t, %1; cvt.u32.u64 %0, t; }" : "=r"(a) : "l"(p));
    return a;
}
__device__ __forceinline__ void cpa16(uint32_t s, const void* g) {
    asm volatile("cp.async.cg.shared.global [%0], [%1], 16;" :: "r"(s), "l"(g));
}
#define CP_COMMIT() asm volatile("cp.async.commit_group;" ::: "memory")
#define CP_WAIT(n)  asm volatile("cp.async.wait_group %0;" :: "n"(n) : "memory")

#define LDSM_X4(r0, r1, r2, r3, addr) \
    asm volatile("ldmatrix.sync.aligned.m8n8.x4.shared.b16 {%0,%1,%2,%3}, [%4];" \
        : "=r"(r0), "=r"(r1), "=r"(r2), "=r"(r3) : "r"(addr))

#define MMA16816(d, a, b) \
    asm volatile("mma.sync.aligned.m16n8k16.row.col.f32.f16.f16.f32 " \
        "{%0,%1,%2,%3},{%4,%5,%6,%7},{%8,%9},{%0,%1,%2,%3};" \
        : "+f"((d)[0]), "+f"((d)[1]), "+f"((d)[2]), "+f"((d)[3]) \
        : "r"((a)[0]), "r"((a)[1]), "r"((a)[2]), "r"((a)[3]), \
          "r"((b)[0]), "r"((b)[1]))

__device__ __forceinline__ uint32_t sw128(uint32_t bo) {
    return bo ^ ((bo >> 3) & 0x70);
}

// ---------------------------------------------------------------------------
// 0) prep: zero accumulators (blocks 0..511) + colsum partials (512..767)
// ---------------------------------------------------------------------------
__global__ void prep_kernel(const float* __restrict__ w,
                            const float* __restrict__ e)
{
    int b = blockIdx.x;
    int tid = threadIdx.x;
    if (b < 512) {
        int i = b * 256 + tid;                       // 0..131071
        g_num[i] = 0.0f;
        g_num[i + 131072] = 0.0f;
        if (i < NCLS) { g_cnt[i] = 0.0f; g_sumA[i] = 0.0f; g_sumNA[i] = 0.0f; }
    } else {
        int cb = b - 512;                            // 0..255
        int z  = cb >> 7;                            // 0..1 (0=e, 1=w)
        int r  = cb & 127;
        int colblk = r & 3;                          // 0..3
        int dblk   = r >> 2;                         // 0..31
        const float* src = (z == 0) ? e : w;
        int col = colblk * 256 + tid;
        int d0  = dblk * 8;
        float s = 0.0f;
        #pragma unroll
        for (int j = 0; j < 8; j++) {
            float v = src[(size_t)(d0 + j) * NCLS + col];
            s += v * v;
        }
        g_cs_part[(z * 32 + dblk) * NCLS + col] = s;
    }
}

// ---------------------------------------------------------------------------
// 1) per-token l2 normalize -> fp16 + class-conditioned scatter (fused)
// ---------------------------------------------------------------------------
__global__ void norm_x_kernel(const float* __restrict__ emb,
                              const int*   __restrict__ labels,
                              const float* __restrict__ anc)
{
    int gwarp = (blockIdx.x * blockDim.x + threadIdx.x) >> 5;
    int lane  = threadIdx.x & 31;
    if (gwarp >= T_TOKENS) return;

    const float* src = emb + (size_t)gwarp * DIM + lane * 8;
    float v[8];
    float4 v0 = *(const float4*)(src);
    float4 v1 = *(const float4*)(src + 4);
    v[0]=v0.x; v[1]=v0.y; v[2]=v0.z; v[3]=v0.w;
    v[4]=v1.x; v[5]=v1.y; v[6]=v1.z; v[7]=v1.w;

    float s = 0.f;
    #pragma unroll
    for (int j = 0; j < 8; j++) s += v[j] * v[j];
    #pragma unroll
    for (int o = 16; o > 0; o >>= 1) s += __shfl_xor_sync(0xFFFFFFFFu, s, o);
    float r = rsqrtf(fmaxf(s, 1e-12f));

    union { __half h[8]; float4 f; } H;
    #pragma unroll
    for (int j = 0; j < 8; j++) {
        v[j] *= r;
        H.h[j] = __float2half_rn(v[j]);
    }
    *(float4*)(g_x16 + (size_t)gwarp * DIM + lane * 8) = H.f;

    float a = anc[gwarp];
    int   c = labels[gwarp];
    if (a > 0.5f) {
        int d0 = lane * 8;
        #pragma unroll
        for (int j = 0; j < 8; j++)
            atomicAdd(&g_num[(d0 + j) * NCLS + c], v[j]);
    }
    if (lane == 0) {
        atomicAdd(&g_cnt[c],   1.0f);
        atomicAdd(&g_sumA[c],  a);
        atomicAdd(&g_sumNA[c], 1.0f - a);
    }
}

// ---------------------------------------------------------------------------
// 2) scale + transpose + fp16 convert: src [d][c] -> g_bt16 [c][d]
//    column rsqrt from the 32 colsum partials (unrolled: loads overlap)
// ---------------------------------------------------------------------------
__global__ void build_bt_kernel(const float* __restrict__ w,
                                const float* __restrict__ e)
{
    __shared__ float tile[32][33];
    __shared__ float rs[32];

    const float* src = (blockIdx.z == 0) ? e : w;
    const int c0 = blockIdx.x * 32;
    const int d0 = blockIdx.y * 32;
    const int tx = threadIdx.x & 31;
    const int ty = threadIdx.x >> 5;

    if (threadIdx.x < 32) {
        int col = c0 + threadIdx.x;
        const float* part = g_cs_part + blockIdx.z * 32 * NCLS + col;
        float s = 0.0f;
        #pragma unroll
        for (int p = 0; p < 32; p++) s += part[p * NCLS];
        rs[threadIdx.x] = rsqrtf(fmaxf(s, 1e-12f));
    }

    #pragma unroll
    for (int i = 0; i < 4; i++) {
        int dl = ty + i * 8;
        tile[dl][tx] = src[(size_t)(d0 + dl) * NCLS + c0 + tx];
    }
    __syncthreads();

    #pragma unroll
    for (int i = 0; i < 4; i++) {
        int cl = ty + i * 8;
        float v = tile[tx][cl] * rs[cl];
        g_bt16[(size_t)(blockIdx.z * NCLS + c0 + cl) * DIM + d0 + tx] = __float2half_rn(v);
    }
}

// ---------------------------------------------------------------------------
// 3) fp16 HMMA GEMM (R12 config) + fused finalize in the prologue shadow.
//    tile 128x128, 4 warps (warp tile 64x64), 128 thr/CTA, 2 CTAs/SM,
//    3-stage cp.async pipeline. grid (256,16): blockIdx.y<8 -> o_cls else o_seq.
// ---------------------------------------------------------------------------
__global__ __launch_bounds__(128, 2)
void gemm_hmma_kernel(float* __restrict__ o_cls, float* __restrict__ o_seq,
                      const float* __restrict__ w, const float* __restrict__ e,
                      float* __restrict__ db)
{
    extern __shared__ char dsm[];
    const int tid    = threadIdx.x;
    const int lane   = tid & 31;
    const int wid    = tid >> 5;    // 0..3
    const int warp_m = wid & 1;     // rows wm*64
    const int warp_n = wid >> 1;    // cols wn*64

    const int m0 = blockIdx.x * BM;
    const int n0 = blockIdx.y * BN;              // fused column space [0,2048)
    float* O = (n0 < NCLS) ? o_cls : o_seq;
    const int ncol0 = n0 & (NCLS - 1);

    uint32_t raw  = smem_u32(dsm);
    uint32_t dynu = (raw + 1023u) & ~1023u;

    // ---- per-thread ldmatrix base addresses (kk = 0), swizzled -------------
    // kk offset (kk*32, bits 5-6) applied by XOR: commutes with SW128 xor
    // because seg*16 (bit 4) and kk*32 (bits 5-6) are bit-disjoint.
    uint32_t a_base[4], b_base[4];
    {
        #pragma unroll
        for (int mf = 0; mf < 4; mf++) {
            int row = warp_m * 64 + mf * 16 + (lane & 15);
            a_base[mf] = sw128((uint32_t)(row * 128 + ((lane >> 4) * 16)));
        }
        int g = lane >> 3;
        #pragma unroll
        for (int bf = 0; bf < 4; bf++) {
            int row = warp_n * 64 + bf * 16 + (g >> 1) * 8 + (lane & 7);
            b_base[bf] = 16384u + sw128((uint32_t)(row * 128 + ((g & 1) * 16)));
        }
    }

    // ---- stage loader: chunk k0=c*64 -> stage (A @0, B @16384) -------------
    const int lr  = tid >> 3;       // 0..15
    const int lsg = tid & 7;        // 16B segment in row
    auto load_stage = [&](int chunk, int stage) {
        uint32_t sb = dynu + stage * STAGE;
        const int k0 = chunk * BK;
        #pragma unroll
        for (int i = 0; i < 8; i++) {
            int r = lr + i * 16;                 // 0..127
            uint32_t sw = sw128((uint32_t)(r * 128 + lsg * 16));
            cpa16(sb + sw,          g_x16  + (size_t)(m0 + r) * DIM + k0 + lsg * 8);
            cpa16(sb + 16384 + sw,  g_bt16 + (size_t)(n0 + r) * DIM + k0 + lsg * 8);
        }
        CP_COMMIT();
    };

    float acc[4][8][4] = {};   // [mfrag][nfrag][4] = 128 regs

    // ---- compute one 64-K chunk from a stage --------------------------------
    auto compute = [&](uint32_t sb) {
        #pragma unroll
        for (int kk = 0; kk < 4; kk++) {
            uint32_t koff = (uint32_t)(kk * 32);
            uint32_t a[4][4], b[8][2];
            #pragma unroll
            for (int mf = 0; mf < 4; mf++)
                LDSM_X4(a[mf][0], a[mf][1], a[mf][2], a[mf][3],
                        (sb + a_base[mf]) ^ koff);
            #pragma unroll
            for (int bf = 0; bf < 4; bf++) {
                uint32_t r0, r1, r2, r3;
                LDSM_X4(r0, r1, r2, r3, (sb + b_base[bf]) ^ koff);
                b[bf*2][0]   = r0; b[bf*2][1]   = r1;
                b[bf*2+1][0] = r2; b[bf*2+1][1] = r3;
            }
            #pragma unroll
            for (int mf = 0; mf < 4; mf++)
                #pragma unroll
                for (int nf = 0; nf < 8; nf++)
                    MMA16816(acc[mf][nf], a[mf], b[nf]);
        }
    };

    // ---- pipeline: 3 stages, 4 chunks ---------------------------------------
    load_stage(0, 0);        // g0
    load_stage(1, 1);        // g1
    load_stage(2, 2);        // g2

    // ---- fused finalize: 64 db elements per CTA, hidden under cp.async ------
    // norm_x completed before this kernel launched (stream order), so
    // g_num / g_cnt / g_sumA / g_sumNA are final.
    {
        int bid = blockIdx.y * gridDim.x + blockIdx.x;   // 0..4095
        int idx = bid * 64 + tid;                        // 64 per CTA
        if (tid < 64) {
            int c = idx & (NCLS - 1);
            float cnt    = g_cnt[c];
            float negAnc = (g_sumA[c]  > 0.5f) ? 1.0f : 0.0f;
            float posAnc = (g_sumNA[c] > 0.5f) ? 1.0f : 0.0f;
            float negCls = (cnt > 0.5f) ? 0.0f : 1.0f;
            float wv = w[idx];
            float ev = e[idx];
            float ema = 0.1f * (g_num[idx] / (cnt + EPS_F));
            db[idx] = ALPHA_F * wv * negAnc + ema + wv * negCls + ev * posAnc;
        }
    }

    CP_WAIT(2); __syncthreads();       // g0 done
    compute(dynu);
    __syncthreads();                   // all warps done reading stage 0
    load_stage(3, 0);                  // g3

    CP_WAIT(2); __syncthreads();       // g1 done
    compute(dynu + STAGE);

    CP_WAIT(1); __syncthreads();       // g2 done
    compute(dynu + 2 * STAGE);

    CP_WAIT(0); __syncthreads();       // g3 done
    compute(dynu);

    // ---- epilogue: vectorized fp32 stores -----------------------------------
    #pragma unroll
    for (int mf = 0; mf < 4; mf++) {
        int row = m0 + warp_m * 64 + mf * 16 + (lane >> 2);
        #pragma unroll
        for (int nf = 0; nf < 8; nf++) {
            int col = ncol0 + warp_n * 64 + nf * 8 + 2 * (lane & 3);
            *(float2*)(O + (size_t)row * NCLS + col) =
                make_float2(acc[mf][nf][0], acc[mf][nf][1]);
            *(float2*)(O + (size_t)(row + 8) * NCLS + col) =
                make_float2(acc[mf][nf][2], acc[mf][nf][3]);
        }
    }
}

// ---------------------------------------------------------------------------
// launch: 4 kernels
// ---------------------------------------------------------------------------
extern "C" void kernel_launch(void* const* d_in, const int* in_sizes, int n_in,
                              void* d_out, int out_size)
{
    const float* emb = (const float*)d_in[0];
    const int*   obj = (const int*)  d_in[2];
    const float* anc = (const float*)d_in[3];
    const float* w   = (const float*)d_in[5];
    const float* e   = (const float*)d_in[6];

    float* out   = (float*)d_out;
    float* o_cls = out;
    float* o_seq = out + (size_t)T_TOKENS * NCLS;
    float* db    = out + (size_t)2 * T_TOKENS * NCLS;

    cudaFuncSetAttribute(gemm_hmma_kernel,
                         cudaFuncAttributeMaxDynamicSharedMemorySize, GEMM_SMEM);

    prep_kernel<<<768, 256>>>(w, e);
    norm_x_kernel<<<(T_TOKENS * 32) / 256, 256>>>(emb, obj, anc);
    build_bt_kernel<<<dim3(32, 8, 2), 256>>>(w, e);

    dim3 grid(T_TOKENS / BM, 2 * NCLS / BN);     // (256, 16)
    gemm_hmma_kernel<<<grid, 128, GEMM_SMEM>>>(o_cls, o_seq, w, e, db);
}

// round 15
// speedup vs baseline: 1.1849x; 1.1188x over previous
#include <cuda_runtime.h>
#include <cuda_fp16.h>
#include <cstdint>

// ---------------------------------------------------------------------------
// B=32, N=1024 -> T=32768 tokens, d=256, C=1024
// o_cls (T x C) = l2norm(x) @ l2norm(e,0)
// o_seq (T x C) = l2norm(x) @ l2norm(w,0)
// new_db (d x C) = EMA codebook update
// GEMM: fp16 mma.sync, tile 128x128, 4 warps (warp tile 64x64), 128 thr/CTA,
// 2 CTAs/SM (R12/R14 config). Finalize fused into the GEMM prologue shadow.
// R15: class-conditioned scatter uses [c][d] accumulator layout +
// red.global.add.v4.f32 (4M scalar atomics -> 1M vector reductions).
// ---------------------------------------------------------------------------

#define T_TOKENS 32768
#define DIM      256
#define NCLS     1024
#define ALPHA_F  0.9f
#define EPS_F    1.19e-07f

// GEMM tiling
#define BM 128
#define BN 128
#define BK 64                       // 64 fp16 = 128 bytes/row (SW128 atom)
#define STAGE  32768                // A 16KB + B 16KB
#define GEMM_SMEM (1024 + 3 * STAGE)   // ~97KB per CTA; x2 CTAs = 194KB/SM

// ---------------- device scratch (allocation-free) -------------------------
__device__ __align__(16) __half g_x16 [(size_t)T_TOKENS * DIM];   // normalized x, fp16
__device__ __align__(16) __half g_bt16[(size_t)2 * NCLS * DIM];   // [class][k]: rows 0..1023 = en, 1024..2047 = wn
__device__ __align__(16) float g_num2[NCLS * DIM];   // [c][d] scatter accumulator
__device__ float g_cnt[NCLS];
__device__ float g_sumA[NCLS];
__device__ float g_sumNA[NCLS];
__device__ float g_cs_part[2 * 32 * NCLS];   // colsum partials [z][dblk][col]

// ---------------- PTX helpers (portable, sm_80+/sm_90+) --------------------
__device__ __forceinline__ uint32_t smem_u32(const void* p) {
    uint32_t a;
    asm("{ .reg .u64 t; cvta.to.shared.u64 t, %1; cvt.u32.u64 %0, t; }" : "=r"(a) : "l"(p));
    return a;
}
__device__ __forceinline__ void cpa16(uint32_t s, const void* g) {
    asm volatile("cp.async.cg.shared.global [%0], [%1], 16;" :: "r"(s), "l"(g));
}
#define CP_COMMIT() asm volatile("cp.async.commit_group;" ::: "memory")
#define CP_WAIT(n)  asm volatile("cp.async.wait_group %0;" :: "n"(n) : "memory")

#define LDSM_X4(r0, r1, r2, r3, addr) \
    asm volatile("ldmatrix.sync.aligned.m8n8.x4.shared.b16 {%0,%1,%2,%3}, [%4];" \
        : "=r"(r0), "=r"(r1), "=r"(r2), "=r"(r3) : "r"(addr))

#define MMA16816(d, a, b) \
    asm volatile("mma.sync.aligned.m16n8k16.row.col.f32.f16.f16.f32 " \
        "{%0,%1,%2,%3},{%4,%5,%6,%7},{%8,%9},{%0,%1,%2,%3};" \
        : "+f"((d)[0]), "+f"((d)[1]), "+f"((d)[2]), "+f"((d)[3]) \
        : "r"((a)[0]), "r"((a)[1]), "r"((a)[2]), "r"((a)[3]), \
          "r"((b)[0]), "r"((b)[1]))

// vectorized global reduction (PTX ISA 8.1, sm_90+): one op, 4 floats
__device__ __forceinline__ void redv4(float* p, float a, float b, float c, float d) {
    asm volatile("red.global.add.v4.f32 [%0], {%1, %2, %3, %4};"
        :: "l"(p), "f"(a), "f"(b), "f"(c), "f"(d) : "memory");
}

__device__ __forceinline__ uint32_t sw128(uint32_t bo) {
    return bo ^ ((bo >> 3) & 0x70);
}

// ---------------------------------------------------------------------------
// 0) prep: zero accumulators (blocks 0..511) + colsum partials (512..767)
// ---------------------------------------------------------------------------
__global__ void prep_kernel(const float* __restrict__ w,
                            const float* __restrict__ e)
{
    int b = blockIdx.x;
    int tid = threadIdx.x;
    if (b < 512) {
        int i = b * 256 + tid;                       // 0..131071
        g_num2[i] = 0.0f;
        g_num2[i + 131072] = 0.0f;
        if (i < NCLS) { g_cnt[i] = 0.0f; g_sumA[i] = 0.0f; g_sumNA[i] = 0.0f; }
    } else {
        int cb = b - 512;                            // 0..255
        int z  = cb >> 7;                            // 0..1 (0=e, 1=w)
        int r  = cb & 127;
        int colblk = r & 3;                          // 0..3
        int dblk   = r >> 2;                         // 0..31
        const float* src = (z == 0) ? e : w;
        int col = colblk * 256 + tid;
        int d0  = dblk * 8;
        float s = 0.0f;
        #pragma unroll
        for (int j = 0; j < 8; j++) {
            float v = src[(size_t)(d0 + j) * NCLS + col];
            s += v * v;
        }
        g_cs_part[(z * 32 + dblk) * NCLS + col] = s;
    }
}

// ---------------------------------------------------------------------------
// 1) per-token l2 normalize -> fp16 + class-conditioned scatter
//    scatter: 2x red.global.add.v4.f32 into [c][d] layout (contiguous dims)
// ---------------------------------------------------------------------------
__global__ void norm_x_kernel(const float* __restrict__ emb,
                              const int*   __restrict__ labels,
                              const float* __restrict__ anc)
{
    int gwarp = (blockIdx.x * blockDim.x + threadIdx.x) >> 5;
    int lane  = threadIdx.x & 31;
    if (gwarp >= T_TOKENS) return;

    const float* src = emb + (size_t)gwarp * DIM + lane * 8;
    float v[8];
    float4 v0 = *(const float4*)(src);
    float4 v1 = *(const float4*)(src + 4);
    v[0]=v0.x; v[1]=v0.y; v[2]=v0.z; v[3]=v0.w;
    v[4]=v1.x; v[5]=v1.y; v[6]=v1.z; v[7]=v1.w;

    float s = 0.f;
    #pragma unroll
    for (int j = 0; j < 8; j++) s += v[j] * v[j];
    #pragma unroll
    for (int o = 16; o > 0; o >>= 1) s += __shfl_xor_sync(0xFFFFFFFFu, s, o);
    float r = rsqrtf(fmaxf(s, 1e-12f));

    union { __half h[8]; float4 f; } H;
    #pragma unroll
    for (int j = 0; j < 8; j++) {
        v[j] *= r;
        H.h[j] = __float2half_rn(v[j]);
    }
    *(float4*)(g_x16 + (size_t)gwarp * DIM + lane * 8) = H.f;

    float a = anc[gwarp];
    int   c = labels[gwarp];
    if (a > 0.5f) {
        float* dst = g_num2 + (size_t)c * DIM + lane * 8;   // 32B-aligned
        redv4(dst,     v[0], v[1], v[2], v[3]);
        redv4(dst + 4, v[4], v[5], v[6], v[7]);
    }
    if (lane == 0) {
        atomicAdd(&g_cnt[c],   1.0f);
        atomicAdd(&g_sumA[c],  a);
        atomicAdd(&g_sumNA[c], 1.0f - a);
    }
}

// ---------------------------------------------------------------------------
// 2) scale + transpose + fp16 convert: src [d][c] -> g_bt16 [c][d]
// ---------------------------------------------------------------------------
__global__ void build_bt_kernel(const float* __restrict__ w,
                                const float* __restrict__ e)
{
    __shared__ float tile[32][33];
    __shared__ float rs[32];

    const float* src = (blockIdx.z == 0) ? e : w;
    const int c0 = blockIdx.x * 32;
    const int d0 = blockIdx.y * 32;
    const int tx = threadIdx.x & 31;
    const int ty = threadIdx.x >> 5;

    if (threadIdx.x < 32) {
        int col = c0 + threadIdx.x;
        const float* part = g_cs_part + blockIdx.z * 32 * NCLS + col;
        float s = 0.0f;
        #pragma unroll
        for (int p = 0; p < 32; p++) s += part[p * NCLS];
        rs[threadIdx.x] = rsqrtf(fmaxf(s, 1e-12f));
    }

    #pragma unroll
    for (int i = 0; i < 4; i++) {
        int dl = ty + i * 8;
        tile[dl][tx] = src[(size_t)(d0 + dl) * NCLS + c0 + tx];
    }
    __syncthreads();

    #pragma unroll
    for (int i = 0; i < 4; i++) {
        int cl = ty + i * 8;
        float v = tile[tx][cl] * rs[cl];
        g_bt16[(size_t)(blockIdx.z * NCLS + c0 + cl) * DIM + d0 + tx] = __float2half_rn(v);
    }
}

// ---------------------------------------------------------------------------
// 3) fp16 HMMA GEMM (R12 config) + fused finalize in the prologue shadow.
// ---------------------------------------------------------------------------
__global__ __launch_bounds__(128, 2)
void gemm_hmma_kernel(float* __restrict__ o_cls, float* __restrict__ o_seq,
                      const float* __restrict__ w, const float* __restrict__ e,
                      float* __restrict__ db)
{
    extern __shared__ char dsm[];
    const int tid    = threadIdx.x;
    const int lane   = tid & 31;
    const int wid    = tid >> 5;    // 0..3
    const int warp_m = wid & 1;     // rows wm*64
    const int warp_n = wid >> 1;    // cols wn*64

    const int m0 = blockIdx.x * BM;
    const int n0 = blockIdx.y * BN;              // fused column space [0,2048)
    float* O = (n0 < NCLS) ? o_cls : o_seq;
    const int ncol0 = n0 & (NCLS - 1);

    uint32_t raw  = smem_u32(dsm);
    uint32_t dynu = (raw + 1023u) & ~1023u;

    // ---- per-thread ldmatrix base addresses (kk = 0), swizzled -------------
    // kk offset (kk*32, bits 5-6) applied by XOR: commutes with SW128 xor
    // because seg*16 (bit 4) and kk*32 (bits 5-6) are bit-disjoint.
    uint32_t a_base[4], b_base[4];
    {
        #pragma unroll
        for (int mf = 0; mf < 4; mf++) {
            int row = warp_m * 64 + mf * 16 + (lane & 15);
            a_base[mf] = sw128((uint32_t)(row * 128 + ((lane >> 4) * 16)));
        }
        int g = lane >> 3;
        #pragma unroll
        for (int bf = 0; bf < 4; bf++) {
            int row = warp_n * 64 + bf * 16 + (g >> 1) * 8 + (lane & 7);
            b_base[bf] = 16384u + sw128((uint32_t)(row * 128 + ((g & 1) * 16)));
        }
    }

    // ---- stage loader: chunk k0=c*64 -> stage (A @0, B @16384) -------------
    const int lr  = tid >> 3;       // 0..15
    const int lsg = tid & 7;        // 16B segment in row
    auto load_stage = [&](int chunk, int stage) {
        uint32_t sb = dynu + stage * STAGE;
        const int k0 = chunk * BK;
        #pragma unroll
        for (int i = 0; i < 8; i++) {
            int r = lr + i * 16;                 // 0..127
            uint32_t sw = sw128((uint32_t)(r * 128 + lsg * 16));
            cpa16(sb + sw,          g_x16  + (size_t)(m0 + r) * DIM + k0 + lsg * 8);
            cpa16(sb + 16384 + sw,  g_bt16 + (size_t)(n0 + r) * DIM + k0 + lsg * 8);
        }
        CP_COMMIT();
    };

    float acc[4][8][4] = {};   // [mfrag][nfrag][4] = 128 regs

    // ---- compute one 64-K chunk from a stage --------------------------------
    auto compute = [&](uint32_t sb) {
        #pragma unroll
        for (int kk = 0; kk < 4; kk++) {
            uint32_t koff = (uint32_t)(kk * 32);
            uint32_t a[4][4], b[8][2];
            #pragma unroll
            for (int mf = 0; mf < 4; mf++)
                LDSM_X4(a[mf][0], a[mf][1], a[mf][2], a[mf][3],
                        (sb + a_base[mf]) ^ koff);
            #pragma unroll
            for (int bf = 0; bf < 4; bf++) {
                uint32_t r0, r1, r2, r3;
                LDSM_X4(r0, r1, r2, r3, (sb + b_base[bf]) ^ koff);
                b[bf*2][0]   = r0; b[bf*2][1]   = r1;
                b[bf*2+1][0] = r2; b[bf*2+1][1] = r3;
            }
            #pragma unroll
            for (int mf = 0; mf < 4; mf++)
                #pragma unroll
                for (int nf = 0; nf < 8; nf++)
                    MMA16816(acc[mf][nf], a[mf], b[nf]);
        }
    };

    // ---- pipeline: 3 stages, 4 chunks ---------------------------------------
    load_stage(0, 0);        // g0
    load_stage(1, 1);        // g1
    load_stage(2, 2);        // g2

    // ---- fused finalize: 64 db elements per CTA, hidden under cp.async ------
    // norm_x completed before this kernel launched (stream order).
    // db is [d][c]; g_num2 is [c][d] -> transposed read (1 MB total, hidden).
    {
        int bid = blockIdx.y * gridDim.x + blockIdx.x;   // 0..4095
        int idx = bid * 64 + tid;                        // 64 per CTA
        if (tid < 64) {
            int c = idx & (NCLS - 1);
            int d = idx >> 10;
            float cnt    = g_cnt[c];
            float negAnc = (g_sumA[c]  > 0.5f) ? 1.0f : 0.0f;
            float posAnc = (g_sumNA[c] > 0.5f) ? 1.0f : 0.0f;
            float negCls = (cnt > 0.5f) ? 0.0f : 1.0f;
            float wv = w[idx];
            float ev = e[idx];
            float ema = 0.1f * (g_num2[c * DIM + d] / (cnt + EPS_F));
            db[idx] = ALPHA_F * wv * negAnc + ema + wv * negCls + ev * posAnc;
        }
    }

    CP_WAIT(2); __syncthreads();       // g0 done
    compute(dynu);
    __syncthreads();                   // all warps done reading stage 0
    load_stage(3, 0);                  // g3

    CP_WAIT(2); __syncthreads();       // g1 done
    compute(dynu + STAGE);

    CP_WAIT(1); __syncthreads();       // g2 done
    compute(dynu + 2 * STAGE);

    CP_WAIT(0); __syncthreads();       // g3 done
    compute(dynu);

    // ---- epilogue: vectorized fp32 stores -----------------------------------
    #pragma unroll
    for (int mf = 0; mf < 4; mf++) {
        int row = m0 + warp_m * 64 + mf * 16 + (lane >> 2);
        #pragma unroll
        for (int nf = 0; nf < 8; nf++) {
            int col = ncol0 + warp_n * 64 + nf * 8 + 2 * (lane & 3);
            *(float2*)(O + (size_t)row * NCLS + col) =
                make_float2(acc[mf][nf][0], acc[mf][nf][1]);
            *(float2*)(O + (size_t)(row + 8) * NCLS + col) =
                make_float2(acc[mf][nf][2], acc[mf][nf][3]);
        }
    }
}

// ---------------------------------------------------------------------------
// launch: 4 kernels
// ---------------------------------------------------------------------------
extern "C" void kernel_launch(void* const* d_in, const int* in_sizes, int n_in,
                              void* d_out, int out_size)
{
    const float* emb = (const float*)d_in[0];
    const int*   obj = (const int*)  d_in[2];
    const float* anc = (const float*)d_in[3];
    const float* w   = (const float*)d_in[5];
    const float* e   = (const float*)d_in[6];

    float* out   = (float*)d_out;
    float* o_cls = out;
    float* o_seq = out + (size_t)T_TOKENS * NCLS;
    float* db    = out + (size_t)2 * T_TOKENS * NCLS;

    cudaFuncSetAttribute(gemm_hmma_kernel,
                         cudaFuncAttributeMaxDynamicSharedMemorySize, GEMM_SMEM);

    prep_kernel<<<768, 256>>>(w, e);
    norm_x_kernel<<<(T_TOKENS * 32) / 256, 256>>>(emb, obj, anc);
    build_bt_kernel<<<dim3(32, 8, 2), 256>>>(w, e);

    dim3 grid(T_TOKENS / BM, 2 * NCLS / BN);     // (256, 16)
    gemm_hmma_kernel<<<grid, 128, GEMM_SMEM>>>(o_cls, o_seq, w, e, db);
}

// round 16
// speedup vs baseline: 1.2053x; 1.0172x over previous
#include <cuda_runtime.h>
#include <cuda_fp16.h>
#include <cstdint>

// ---------------------------------------------------------------------------
// B=32, N=1024 -> T=32768 tokens, d=256, C=1024
// o_cls (T x C) = l2norm(x) @ l2norm(e,0)
// o_seq (T x C) = l2norm(x) @ l2norm(w,0)
// new_db (d x C) = EMA codebook update
// 3 launches: prep -> fused(norm_x || build_bt) -> gemm(+finalize in shadow)
// GEMM: fp16 mma.sync, tile 128x128, 4 warps (warp tile 64x64), 128 thr/CTA,
// 2 CTAs/SM. Scatter: red.global.add.v4.f32 into [c][d] accumulator.
// ---------------------------------------------------------------------------

#define T_TOKENS 32768
#define DIM      256
#define NCLS     1024
#define ALPHA_F  0.9f
#define EPS_F    1.19e-07f

// GEMM tiling
#define BM 128
#define BN 128
#define BK 64                       // 64 fp16 = 128 bytes/row (SW128 atom)
#define STAGE  32768                // A 16KB + B 16KB
#define GEMM_SMEM (1024 + 3 * STAGE)   // ~97KB per CTA; x2 CTAs = 194KB/SM

// ---------------- device scratch (allocation-free) -------------------------
__device__ __align__(16) __half g_x16 [(size_t)T_TOKENS * DIM];   // normalized x, fp16
__device__ __align__(16) __half g_bt16[(size_t)2 * NCLS * DIM];   // [class][k]: rows 0..1023 = en, 1024..2047 = wn
__device__ __align__(16) float g_num2[NCLS * DIM];   // [c][d] scatter accumulator
__device__ float g_cnt[NCLS];
__device__ float g_sumA[NCLS];
__device__ float g_sumNA[NCLS];
__device__ float g_cs_part[2 * 32 * NCLS];   // colsum partials [z][dblk][col]

// ---------------- PTX helpers (portable, sm_80+/sm_90+) --------------------
__device__ __forceinline__ uint32_t smem_u32(const void* p) {
    uint32_t a;
    asm("{ .reg .u64 t; cvta.to.shared.u64 t, %1; cvt.u32.u64 %0, t; }" : "=r"(a) : "l"(p));
    return a;
}
__device__ __forceinline__ void cpa16(uint32_t s, const void* g) {
    asm volatile("cp.async.cg.shared.global [%0], [%1], 16;" :: "r"(s), "l"(g));
}
#define CP_COMMIT() asm volatile("cp.async.commit_group;" ::: "memory")
#define CP_WAIT(n)  asm volatile("cp.async.wait_group %0;" :: "n"(n) : "memory")

#define LDSM_X4(r0, r1, r2, r3, addr) \
    asm volatile("ldmatrix.sync.aligned.m8n8.x4.shared.b16 {%0,%1,%2,%3}, [%4];" \
        : "=r"(r0), "=r"(r1), "=r"(r2), "=r"(r3) : "r"(addr))

#define MMA16816(d, a, b) \
    asm volatile("mma.sync.aligned.m16n8k16.row.col.f32.f16.f16.f32 " \
        "{%0,%1,%2,%3},{%4,%5,%6,%7},{%8,%9},{%0,%1,%2,%3};" \
        : "+f"((d)[0]), "+f"((d)[1]), "+f"((d)[2]), "+f"((d)[3]) \
        : "r"((a)[0]), "r"((a)[1]), "r"((a)[2]), "r"((a)[3]), \
          "r"((b)[0]), "r"((b)[1]))

// vectorized global reduction (PTX ISA 8.1, sm_90+): one op, 4 floats
__device__ __forceinline__ void redv4(float* p, float a, float b, float c, float d) {
    asm volatile("red.global.add.v4.f32 [%0], {%1, %2, %3, %4};"
        :: "l"(p), "f"(a), "f"(b), "f"(c), "f"(d) : "memory");
}

__device__ __forceinline__ uint32_t sw128(uint32_t bo) {
    return bo ^ ((bo >> 3) & 0x70);
}

// ---------------------------------------------------------------------------
// 0) prep: zero accumulators (blocks 0..511) + colsum partials (512..767)
// ---------------------------------------------------------------------------
__global__ void prep_kernel(const float* __restrict__ w,
                            const float* __restrict__ e)
{
    int b = blockIdx.x;
    int tid = threadIdx.x;
    if (b < 512) {
        int i = b * 256 + tid;                       // 0..131071
        g_num2[i] = 0.0f;
        g_num2[i + 131072] = 0.0f;
        if (i < NCLS) { g_cnt[i] = 0.0f; g_sumA[i] = 0.0f; g_sumNA[i] = 0.0f; }
    } else {
        int cb = b - 512;                            // 0..255
        int z  = cb >> 7;                            // 0..1 (0=e, 1=w)
        int r  = cb & 127;
        int colblk = r & 3;                          // 0..3
        int dblk   = r >> 2;                         // 0..31
        const float* src = (z == 0) ? e : w;
        int col = colblk * 256 + tid;
        int d0  = dblk * 8;
        float s = 0.0f;
        #pragma unroll
        for (int j = 0; j < 8; j++) {
            float v = src[(size_t)(d0 + j) * NCLS + col];
            s += v * v;
        }
        g_cs_part[(z * 32 + dblk) * NCLS + col] = s;
    }
}

// ---------------------------------------------------------------------------
// 1) fused: norm_x (blocks 0..4095) || build_bt (blocks 4096..4607)
//    independent workloads, one launch -> build_bt hides inside norm_x
// ---------------------------------------------------------------------------
__global__ void fused_norm_bt_kernel(const float* __restrict__ emb,
                                     const int*   __restrict__ labels,
                                     const float* __restrict__ anc,
                                     const float* __restrict__ w,
                                     const float* __restrict__ e)
{
    __shared__ float tile[32][33];
    __shared__ float rs[32];

    if (blockIdx.x < 4096) {
        // ---------------- norm_x: 8 tokens per block -----------------------
        int gwarp = (blockIdx.x * blockDim.x + threadIdx.x) >> 5;
        int lane  = threadIdx.x & 31;

        const float* src = emb + (size_t)gwarp * DIM + lane * 8;
        float v[8];
        float4 v0 = *(const float4*)(src);
        float4 v1 = *(const float4*)(src + 4);
        v[0]=v0.x; v[1]=v0.y; v[2]=v0.z; v[3]=v0.w;
        v[4]=v1.x; v[5]=v1.y; v[6]=v1.z; v[7]=v1.w;

        float s = 0.f;
        #pragma unroll
        for (int j = 0; j < 8; j++) s += v[j] * v[j];
        #pragma unroll
        for (int o = 16; o > 0; o >>= 1) s += __shfl_xor_sync(0xFFFFFFFFu, s, o);
        float r = rsqrtf(fmaxf(s, 1e-12f));

        union { __half h[8]; float4 f; } H;
        #pragma unroll
        for (int j = 0; j < 8; j++) {
            v[j] *= r;
            H.h[j] = __float2half_rn(v[j]);
        }
        *(float4*)(g_x16 + (size_t)gwarp * DIM + lane * 8) = H.f;

        float a = anc[gwarp];
        int   c = labels[gwarp];
        if (a > 0.5f) {
            float* dst = g_num2 + (size_t)c * DIM + lane * 8;   // 32B-aligned
            redv4(dst,     v[0], v[1], v[2], v[3]);
            redv4(dst + 4, v[4], v[5], v[6], v[7]);
        }
        if (lane == 0) {
            atomicAdd(&g_cnt[c],   1.0f);
            atomicAdd(&g_sumA[c],  a);
            atomicAdd(&g_sumNA[c], 1.0f - a);
        }
    } else {
        // ---------------- build_bt: 512 blocks ------------------------------
        int cb = blockIdx.x - 4096;          // 0..511
        int bz = cb >> 8;                    // 0..1 (0=e, 1=w)
        int rr = cb & 255;
        int bx = rr & 31;                    // 0..31 c-tile
        int by = rr >> 5;                    // 0..7  d-tile

        const float* src = (bz == 0) ? e : w;
        const int c0 = bx * 32;
        const int d0 = by * 32;
        const int tx = threadIdx.x & 31;
        const int ty = threadIdx.x >> 5;

        if (threadIdx.x < 32) {
            int col = c0 + threadIdx.x;
            const float* part = g_cs_part + bz * 32 * NCLS + col;
            float s = 0.0f;
            #pragma unroll
            for (int p = 0; p < 32; p++) s += part[p * NCLS];
            rs[threadIdx.x] = rsqrtf(fmaxf(s, 1e-12f));
        }

        #pragma unroll
        for (int i = 0; i < 4; i++) {
            int dl = ty + i * 8;
            tile[dl][tx] = src[(size_t)(d0 + dl) * NCLS + c0 + tx];
        }
        __syncthreads();

        #pragma unroll
        for (int i = 0; i < 4; i++) {
            int cl = ty + i * 8;
            float v = tile[tx][cl] * rs[cl];
            g_bt16[(size_t)(bz * NCLS + c0 + cl) * DIM + d0 + tx] = __float2half_rn(v);
        }
    }
}

// ---------------------------------------------------------------------------
// 2) fp16 HMMA GEMM (R12 config) + fused finalize in the prologue shadow.
// ---------------------------------------------------------------------------
__global__ __launch_bounds__(128, 2)
void gemm_hmma_kernel(float* __restrict__ o_cls, float* __restrict__ o_seq,
                      const float* __restrict__ w, const float* __restrict__ e,
                      float* __restrict__ db)
{
    extern __shared__ char dsm[];
    const int tid    = threadIdx.x;
    const int lane   = tid & 31;
    const int wid    = tid >> 5;    // 0..3
    const int warp_m = wid & 1;     // rows wm*64
    const int warp_n = wid >> 1;    // cols wn*64

    const int m0 = blockIdx.x * BM;
    const int n0 = blockIdx.y * BN;              // fused column space [0,2048)
    float* O = (n0 < NCLS) ? o_cls : o_seq;
    const int ncol0 = n0 & (NCLS - 1);

    uint32_t raw  = smem_u32(dsm);
    uint32_t dynu = (raw + 1023u) & ~1023u;

    // ---- per-thread ldmatrix base addresses (kk = 0), swizzled -------------
    // kk offset (kk*32, bits 5-6) applied by XOR: commutes with SW128 xor
    // because seg*16 (bit 4) and kk*32 (bits 5-6) are bit-disjoint.
    uint32_t a_base[4], b_base[4];
    {
        #pragma unroll
        for (int mf = 0; mf < 4; mf++) {
            int row = warp_m * 64 + mf * 16 + (lane & 15);
            a_base[mf] = sw128((uint32_t)(row * 128 + ((lane >> 4) * 16)));
        }
        int g = lane >> 3;
        #pragma unroll
        for (int bf = 0; bf < 4; bf++) {
            int row = warp_n * 64 + bf * 16 + (g >> 1) * 8 + (lane & 7);
            b_base[bf] = 16384u + sw128((uint32_t)(row * 128 + ((g & 1) * 16)));
        }
    }

    // ---- stage loader: chunk k0=c*64 -> stage (A @0, B @16384) -------------
    const int lr  = tid >> 3;       // 0..15
    const int lsg = tid & 7;        // 16B segment in row
    auto load_stage = [&](int chunk, int stage) {
        uint32_t sb = dynu + stage * STAGE;
        const int k0 = chunk * BK;
        #pragma unroll
        for (int i = 0; i < 8; i++) {
            int r = lr + i * 16;                 // 0..127
            uint32_t sw = sw128((uint32_t)(r * 128 + lsg * 16));
            cpa16(sb + sw,          g_x16  + (size_t)(m0 + r) * DIM + k0 + lsg * 8);
            cpa16(sb + 16384 + sw,  g_bt16 + (size_t)(n0 + r) * DIM + k0 + lsg * 8);
        }
        CP_COMMIT();
    };

    float acc[4][8][4] = {};   // [mfrag][nfrag][4] = 128 regs

    // ---- compute one 64-K chunk from a stage --------------------------------
    auto compute = [&](uint32_t sb) {
        #pragma unroll
        for (int kk = 0; kk < 4; kk++) {
            uint32_t koff = (uint32_t)(kk * 32);
            uint32_t a[4][4], b[8][2];
            #pragma unroll
            for (int mf = 0; mf < 4; mf++)
                LDSM_X4(a[mf][0], a[mf][1], a[mf][2], a[mf][3],
                        (sb + a_base[mf]) ^ koff);
            #pragma unroll
            for (int bf = 0; bf < 4; bf++) {
                uint32_t r0, r1, r2, r3;
                LDSM_X4(r0, r1, r2, r3, (sb + b_base[bf]) ^ koff);
                b[bf*2][0]   = r0; b[bf*2][1]   = r1;
                b[bf*2+1][0] = r2; b[bf*2+1][1] = r3;
            }
            #pragma unroll
            for (int mf = 0; mf < 4; mf++)
                #pragma unroll
                for (int nf = 0; nf < 8; nf++)
                    MMA16816(acc[mf][nf], a[mf], b[nf]);
        }
    };

    // ---- pipeline: 3 stages, 4 chunks ---------------------------------------
    load_stage(0, 0);        // g0
    load_stage(1, 1);        // g1
    load_stage(2, 2);        // g2

    // ---- fused finalize: 64 db elements per CTA, hidden under cp.async ------
    // fused_norm_bt completed before this kernel launched (stream order).
    // db is [d][c]; g_num2 is [c][d] -> transposed read (1 MB total, hidden).
    {
        int bid = blockIdx.y * gridDim.x + blockIdx.x;   // 0..4095
        int idx = bid * 64 + tid;                        // 64 per CTA
        if (tid < 64) {
            int c = idx & (NCLS - 1);
            int d = idx >> 10;
            float cnt    = g_cnt[c];
            float negAnc = (g_sumA[c]  > 0.5f) ? 1.0f : 0.0f;
            float posAnc = (g_sumNA[c] > 0.5f) ? 1.0f : 0.0f;
            float negCls = (cnt > 0.5f) ? 0.0f : 1.0f;
            float wv = w[idx];
            float ev = e[idx];
            float ema = 0.1f * (g_num2[c * DIM + d] / (cnt + EPS_F));
            db[idx] = ALPHA_F * wv * negAnc + ema + wv * negCls + ev * posAnc;
        }
    }

    CP_WAIT(2); __syncthreads();       // g0 done
    compute(dynu);
    __syncthreads();                   // all warps done reading stage 0
    load_stage(3, 0);                  // g3

    CP_WAIT(2); __syncthreads();       // g1 done
    compute(dynu + STAGE);

    CP_WAIT(1); __syncthreads();       // g2 done
    compute(dynu + 2 * STAGE);

    CP_WAIT(0); __syncthreads();       // g3 done
    compute(dynu);

    // ---- epilogue: vectorized fp32 stores -----------------------------------
    #pragma unroll
    for (int mf = 0; mf < 4; mf++) {
        int row = m0 + warp_m * 64 + mf * 16 + (lane >> 2);
        #pragma unroll
        for (int nf = 0; nf < 8; nf++) {
            int col = ncol0 + warp_n * 64 + nf * 8 + 2 * (lane & 3);
            *(float2*)(O + (size_t)row * NCLS + col) =
                make_float2(acc[mf][nf][0], acc[mf][nf][1]);
            *(float2*)(O + (size_t)(row + 8) * NCLS + col) =
                make_float2(acc[mf][nf][2], acc[mf][nf][3]);
        }
    }
}

// ---------------------------------------------------------------------------
// launch: 3 kernels
// ---------------------------------------------------------------------------
extern "C" void kernel_launch(void* const* d_in, const int* in_sizes, int n_in,
                              void* d_out, int out_size)
{
    const float* emb = (const float*)d_in[0];
    const int*   obj = (const int*)  d_in[2];
    const float* anc = (const float*)d_in[3];
    const float* w   = (const float*)d_in[5];
    const float* e   = (const float*)d_in[6];

    float* out   = (float*)d_out;
    float* o_cls = out;
    float* o_seq = out + (size_t)T_TOKENS * NCLS;
    float* db    = out + (size_t)2 * T_TOKENS * NCLS;

    cudaFuncSetAttribute(gemm_hmma_kernel,
                         cudaFuncAttributeMaxDynamicSharedMemorySize, GEMM_SMEM);

    prep_kernel<<<768, 256>>>(w, e);
    fused_norm_bt_kernel<<<4608, 256>>>(emb, obj, anc, w, e);

    dim3 grid(T_TOKENS / BM, 2 * NCLS / BN);     // (256, 16)
    gemm_hmma_kernel<<<grid, 128, GEMM_SMEM>>>(o_cls, o_seq, w, e, db);
}